// round 7
// baseline (speedup 1.0000x reference)
#include <cuda_runtime.h>

#define NN        37449   // total nodes
#define L5_START  4681    // leaf level start
#define L5_COUNT  32768
#define L4_START  585
#define L4_COUNT  4096
#define L3_START  73
#define L2_START  9
#define L1_START  1

#define NT        768     // threads per block (24 warps)
#define NW        24      // warps per block

// sigmoid(w) for all nodes (internal-level dots + head/tail scalars)
__device__ float g_sw[NN];
// 4 shifted copies of the leaf section: copy s stores leaf l at index
// ((4-s)&3)+l. For LB=s, vector k's leaves start at copy index
// ((4-s)&3)+s+4k (= 4+4k for s>0, 4k for s=0) -> 16B aligned.
__device__ __align__(16) float g_swl[4][L5_COUNT + 4];

__global__ void setup_kernel(const float* __restrict__ w) {
    int i = blockIdx.x * blockDim.x + threadIdx.x;
    if (i >= NN) return;
    float sv = 1.0f / (1.0f + __expf(-w[i]));
    g_sw[i] = sv;
    int l = i - L5_START;
    if (l >= 0) {
        #pragma unroll
        for (int s = 0; s < 4; ++s)
            g_swl[s][((4 - s) & 3) + l] = sv;
    }
}

// Per-vector parent-contribution math. Vector k covers leaves [LB+4k, LB+4k+4).
// s = full 4-dot, a = low-parent part, b = high-parent part.
template<int LB>
__device__ __forceinline__ void vec_contrib(const float4& x, const float4& sv,
                                            int k, float& s, float& a, float& b)
{
    float q0 = x.x * sv.x, q1 = x.y * sv.y, q2 = x.z * sv.z, q3 = x.w * sv.w;
    s = (q0 + q1) + (q2 + q3);
    if (LB == 0) {
        a = s; b = 0.f;
    } else {
        float ao, bo;
        if (LB == 1) { ao = (q0 + q1) + q2; bo = q3; }
        if (LB == 2) { ao = q0 + q1;        bo = q2 + q3; }
        if (LB == 3) { ao = q0;             bo = (q1 + q2) + q3; }
        bool odd = (k & 1);
        a = odd ? ao : s;
        b = odd ? bo : 0.f;
    }
}

// Warp handles 32 consecutive vectors (group g = k>>5) -> 16 parents at
// s_l4[16g .. 16g+16): parent slot m = b[2m-1] + s[2m] + a[2m+1].
template<int LB>
__device__ __forceinline__ void emit_parents(float s, float a, float b,
                                             float* __restrict__ s_l4,
                                             float* __restrict__ s_edge,
                                             int g, int lane)
{
    float ss = __shfl_sync(0xffffffffu, s, (2 * lane)      & 31);
    float aa = __shfl_sync(0xffffffffu, a, (2 * lane + 1)  & 31);
    float bb = __shfl_sync(0xffffffffu, b, (2 * lane + 31) & 31);
    if (lane < 16) {
        float val = ss + aa;
        if (lane > 0) val += bb;            // lane-0 parents get b in fixup pass
        s_l4[g * 16 + lane] = val;
    }
    if (LB != 0 && lane == 31)
        s_edge[g + 1] = b;                  // edge into next group's first parent
}

template<int LB>
__device__ __forceinline__ void stream_phase(
    const float* __restrict__ rin, float* __restrict__ rout,
    float* __restrict__ s_l4, float* __restrict__ s_edge, int tid)
{
    const float4* __restrict__ in4  = reinterpret_cast<const float4*>(rin  + L5_START + LB);
    float4*       __restrict__ out4 = reinterpret_cast<float4*>(rout + L5_START + LB);
    // 16B-aligned base: copy index ((4-LB)&3)+LB  (0 for LB==0, 4 otherwise)
    const float4* __restrict__ sw4  =
        reinterpret_cast<const float4*>(&g_swl[LB][((4 - LB) & 3) + LB]);
    const int lane = tid & 31;
    const int warp = tid >> 5;

    // ---- 10 full iterations x 768 vectors = 7680 (default-cached ld/st:
    // L2 keeps replay-invariant input, absorbs rewritten output lines) ----
    #pragma unroll 5
    for (int it = 0; it < 10; ++it) {
        const int k = it * NT + tid;
        float4 x  = __ldg(in4 + k);
        float4 sv = __ldg(sw4 + k);
        out4[k] = x;
        float s, a, b;
        vec_contrib<LB>(x, sv, k, s, a, b);
        emit_parents<LB>(s, a, b, s_l4, s_edge, it * NW + warp, lane);
    }

    // ---- Tail: vectors 7680..8191 handled by warps 0..15 (full warps).
    if (tid < 512) {
        const int k = 7680 + tid;
        float4 x, sv;
        if (LB == 0 || k != 8191) {
            x  = __ldg(in4 + k);
            sv = __ldg(sw4 + k);
            out4[k] = x;
        } else {
            // Clipped final vector: only leaves LB+32764 .. 32767 exist.
            float xt[4] = {0.f, 0.f, 0.f, 0.f};
            float st[4] = {0.f, 0.f, 0.f, 0.f};
            const float* rp = rin  + L5_START + LB + 32764;
            float*       wp = rout + L5_START + LB + 32764;
            const float* sp = &g_swl[LB][((4 - LB) & 3) + LB + 32764];
            #pragma unroll
            for (int j = 0; j < 4 - LB; ++j) {
                xt[j] = rp[j]; st[j] = sp[j]; wp[j] = xt[j];
            }
            x  = make_float4(xt[0], xt[1], xt[2], xt[3]);
            sv = make_float4(st[0], st[1], st[2], st[3]);
        }
        float s, a, b;
        vec_contrib<LB>(x, sv, k, s, a, b);
        emit_parents<LB>(s, a, b, s_l4, s_edge, 240 + warp, lane);
    }

    if (LB != 0 && tid == 0) {
        // Head leaves 0..LB-1 belong to parent 0.
        float h = 0.f;
        #pragma unroll
        for (int j = 0; j < LB; ++j) {
            float xv = rin[L5_START + j];
            rout[L5_START + j] = xv;
            h += xv * g_sw[L5_START + j];
        }
        s_edge[0] = h;
    }
}

__global__ __launch_bounds__(NT, 2)
void tree_kernel(const float* __restrict__ in, float* __restrict__ out)
{
    __shared__ __align__(16) float s_l4[L4_COUNT];   // raw (pre-clamp) parent sums
    __shared__ float s_edge[260];
    __shared__ __align__(16) float s_l3[512];
    __shared__ __align__(16) float s_l2[64];
    __shared__ __align__(16) float s_l1[8];

    const int tid = threadIdx.x;
    const int r   = blockIdx.x;
    const float* __restrict__ rin  = in  + (size_t)r * NN;
    float*       __restrict__ rout = out + (size_t)r * NN;
    const int lb = (4 - ((r + 1) & 3)) & 3;   // leaf-base alignment for this row

    switch (lb) {
        case 0: stream_phase<0>(rin, rout, s_l4, s_edge, tid); break;
        case 1: stream_phase<1>(rin, rout, s_l4, s_edge, tid); break;
        case 2: stream_phase<2>(rin, rout, s_l4, s_edge, tid); break;
        default: stream_phase<3>(rin, rout, s_l4, s_edge, tid); break;
    }
    __syncthreads();
    if (lb != 0 && tid < 256) s_l4[tid * 16] += s_edge[tid];  // add b-edges
    __syncthreads();

    // ---- Level 3: 512 parents from clamped L4 values ----
    if (tid < 512) {
        const float4* p = reinterpret_cast<const float4*>(s_l4) + 2 * tid;
        float4 va = p[0], vb = p[1];
        float c0 = __saturatef(va.x), c1 = __saturatef(va.y);
        float c2 = __saturatef(va.z), c3 = __saturatef(va.w);
        float c4 = __saturatef(vb.x), c5 = __saturatef(vb.y);
        float c6 = __saturatef(vb.z), c7 = __saturatef(vb.w);
        const float* swp = g_sw + L4_START + 8 * tid;
        float v = c0 * __ldg(swp + 0) + c1 * __ldg(swp + 1)
                + c2 * __ldg(swp + 2) + c3 * __ldg(swp + 3)
                + c4 * __ldg(swp + 4) + c5 * __ldg(swp + 5)
                + c6 * __ldg(swp + 6) + c7 * __ldg(swp + 7);
        s_l3[tid] = __saturatef(v);
    }
    __syncthreads();

    // ---- Level 2 ----
    if (tid < 64) {
        const float4* p = reinterpret_cast<const float4*>(s_l3) + 2 * tid;
        float4 va = p[0], vb = p[1];
        const float* swp = g_sw + L3_START + 8 * tid;
        float v = va.x * __ldg(swp + 0) + va.y * __ldg(swp + 1)
                + va.z * __ldg(swp + 2) + va.w * __ldg(swp + 3)
                + vb.x * __ldg(swp + 4) + vb.y * __ldg(swp + 5)
                + vb.z * __ldg(swp + 6) + vb.w * __ldg(swp + 7);
        s_l2[tid] = __saturatef(v);
    }
    __syncthreads();

    // ---- Level 1 ----
    if (tid < 8) {
        const float4* p = reinterpret_cast<const float4*>(s_l2) + 2 * tid;
        float4 va = p[0], vb = p[1];
        const float* swp = g_sw + L2_START + 8 * tid;
        float v = va.x * __ldg(swp + 0) + va.y * __ldg(swp + 1)
                + va.z * __ldg(swp + 2) + va.w * __ldg(swp + 3)
                + vb.x * __ldg(swp + 4) + vb.y * __ldg(swp + 5)
                + vb.z * __ldg(swp + 6) + vb.w * __ldg(swp + 7);
        s_l1[tid] = __saturatef(v);
    }
    __syncthreads();

    // ---- Root ----
    if (tid == 0) {
        const float4* p = reinterpret_cast<const float4*>(s_l1);
        float4 va = p[0], vb = p[1];
        const float* swp = g_sw + L1_START;
        float v = va.x * __ldg(swp + 0) + va.y * __ldg(swp + 1)
                + va.z * __ldg(swp + 2) + va.w * __ldg(swp + 3)
                + vb.x * __ldg(swp + 4) + vb.y * __ldg(swp + 5)
                + vb.z * __ldg(swp + 6) + vb.w * __ldg(swp + 7);
        rout[0] = __saturatef(v);
    }

    // ---- Write internal levels (coalesced) ----
    for (int i = tid; i < L4_COUNT; i += NT)
        rout[L4_START + i] = __saturatef(s_l4[i]);
    if (tid < 512) rout[L3_START + tid] = s_l3[tid];
    if (tid < 64)  rout[L2_START + tid] = s_l2[tid];
    if (tid < 8)   rout[L1_START + tid] = s_l1[tid];
}

extern "C" void kernel_launch(void* const* d_in, const int* in_sizes, int n_in,
                              void* d_out, int out_size) {
    const float* probs = (const float*)d_in[0];   // [2048, 37449] fp32
    const float* w     = (const float*)d_in[1];   // [37449] fp32
    float* out         = (float*)d_out;

    const int batch = in_sizes[0] / NN;           // 2048

    setup_kernel<<<(NN + 255) / 256, 256>>>(w);
    tree_kernel<<<batch, NT>>>(probs, out);
}

// round 9
// speedup vs baseline: 1.0641x; 1.0641x over previous
#include <cuda_runtime.h>
#include <cstdint>

#define NN        37449   // total nodes
#define L5_START  4681    // leaf level start
#define L5_COUNT  32768
#define L4_START  585
#define L4_COUNT  4096
#define L3_START  73
#define L2_START  9
#define L1_START  1

// sigmoid(w) for all nodes (internal-level dots + head/tail scalars)
__device__ float g_sw[NN];
// 8 shifted copies of the leaf section: copy s stores leaf l at index
// ((8-s)&7)+l. For LB8=s, vector k's 8 leaves start at copy index
// ((8-s)&7)+s+8k (= 8+8k for s>0, 8k for s=0) -> 32B aligned.
// Row length 32776 floats = 131104 B = 32*4097 -> every row 32B aligned.
__device__ __align__(32) float g_swl8[8][L5_COUNT + 8];

__global__ void setup_kernel(const float* __restrict__ w) {
    int i = blockIdx.x * blockDim.x + threadIdx.x;
    if (i >= NN) return;
    float sv = 1.0f / (1.0f + __expf(-w[i]));
    g_sw[i] = sv;
    int l = i - L5_START;
    if (l >= 0) {
        #pragma unroll
        for (int s = 0; s < 8; ++s)
            g_swl8[s][((8 - s) & 7) + l] = sv;
    }
}

// ---- 256-bit global memory ops (sm_100+) ----
__device__ __forceinline__ void ldg256(float* v, const float* p) {
    asm volatile("ld.global.nc.v8.f32 {%0,%1,%2,%3,%4,%5,%6,%7}, [%8];"
                 : "=f"(v[0]), "=f"(v[1]), "=f"(v[2]), "=f"(v[3]),
                   "=f"(v[4]), "=f"(v[5]), "=f"(v[6]), "=f"(v[7])
                 : "l"(p));
}
__device__ __forceinline__ void stg256(float* p, const float* v) {
    asm volatile("st.global.v8.f32 [%0], {%1,%2,%3,%4,%5,%6,%7,%8};"
                 :: "l"(p), "f"(v[0]), "f"(v[1]), "f"(v[2]), "f"(v[3]),
                    "f"(v[4]), "f"(v[5]), "f"(v[6]), "f"(v[7])
                 : "memory");
}

// Vector k covers leaves [LB8+8k, LB8+8k+8): a -> parent k (first 8-LB8
// products), b -> parent k+1 (last LB8 products). Parent k = a[k] + b[k-1].
template<int LB8>
__device__ __forceinline__ void vec_ab(const float* x, const float* sv,
                                       float& a, float& b)
{
    float p[8];
    #pragma unroll
    for (int i = 0; i < 8; ++i) p[i] = x[i] * sv[i];
    a = 0.f; b = 0.f;
    #pragma unroll
    for (int i = 0; i < 8 - LB8; ++i) a += p[i];
    #pragma unroll
    for (int i = 8 - LB8; i < 8; ++i) b += p[i];
}

template<int LB8>
__device__ __forceinline__ void emit(float a, float b, int k,
                                     float* __restrict__ s_l4,
                                     float* __restrict__ s_edge, int lane)
{
    if (LB8 == 0) {
        s_l4[k] = a;                       // vector k IS parent k
    } else {
        float bprev = __shfl_up_sync(0xffffffffu, b, 1);
        float val = a;
        if (lane > 0) val += bprev;        // lane-0 parents patched in fixup
        s_l4[k] = val;
        if (lane == 31) s_edge[(k >> 5) + 1] = b;  // feeds parent k+1
    }
}

template<int LB8>
__device__ __forceinline__ void stream_phase(
    const float* __restrict__ rin, float* __restrict__ rout,
    float* __restrict__ s_l4, float* __restrict__ s_edge, int tid)
{
    const float* __restrict__ xb  = rin  + L5_START + LB8;   // 32B aligned
    float*       __restrict__ ob  = rout + L5_START + LB8;   // 32B aligned
    const float* __restrict__ swb = &g_swl8[LB8][LB8 ? 8 : 0];
    const int lane = tid & 31;

    const int NFULL = (LB8 == 0) ? 8 : 7;   // full 512-vector iterations
    #pragma unroll 2
    for (int it = 0; it < NFULL; ++it) {
        const int k = it * 512 + tid;
        float x[8], sv[8];
        ldg256(x,  xb  + 8 * k);
        ldg256(sv, swb + 8 * k);
        stg256(ob + 8 * k, x);
        float a, b;
        vec_ab<LB8>(x, sv, a, b);
        emit<LB8>(a, b, k, s_l4, s_edge, lane);
    }

    if (LB8 != 0) {
        // Peeled it==7: vector 4095 is clipped (only 8-LB8 leaves exist).
        const int k = 7 * 512 + tid;
        float a, b;
        if (k != 4095) {
            float x[8], sv[8];
            ldg256(x,  xb  + 8 * k);
            ldg256(sv, swb + 8 * k);
            stg256(ob + 8 * k, x);
            vec_ab<LB8>(x, sv, a, b);
        } else {
            const float* rp = xb  + 8 * 4095;
            float*       wp = ob  + 8 * 4095;
            const float* sp = swb + 8 * 4095;
            a = 0.f; b = 0.f;
            #pragma unroll
            for (int j = 0; j < 8 - LB8; ++j) {
                float xv = rp[j];
                wp[j] = xv;
                a += xv * sp[j];
            }
        }
        emit<LB8>(a, b, k, s_l4, s_edge, lane);

        if (tid == 0) {
            // Head leaves 0..LB8-1 belong to parent 0.
            float h = 0.f;
            #pragma unroll
            for (int j = 0; j < LB8; ++j) {
                float xv = rin[L5_START + j];
                rout[L5_START + j] = xv;
                h += xv * g_sw[L5_START + j];
            }
            s_edge[0] = h;
        }
    }
}

__global__ __launch_bounds__(512)
void tree_kernel(const float* __restrict__ in, float* __restrict__ out)
{
    __shared__ __align__(16) float s_l4[L4_COUNT];   // raw (pre-clamp) sums
    __shared__ float s_edge[132];
    __shared__ __align__(16) float s_l3[512];
    __shared__ __align__(16) float s_l2[64];
    __shared__ __align__(16) float s_l1[8];

    const int tid = threadIdx.x;
    const int r   = blockIdx.x;
    const float* __restrict__ rin  = in  + (size_t)r * NN;
    float*       __restrict__ rout = out + (size_t)r * NN;
    const int lb8 = (8 - ((r + 1) & 7)) & 7;   // leaf-base alignment mod 8

    switch (lb8) {
        case 0: stream_phase<0>(rin, rout, s_l4, s_edge, tid); break;
        case 1: stream_phase<1>(rin, rout, s_l4, s_edge, tid); break;
        case 2: stream_phase<2>(rin, rout, s_l4, s_edge, tid); break;
        case 3: stream_phase<3>(rin, rout, s_l4, s_edge, tid); break;
        case 4: stream_phase<4>(rin, rout, s_l4, s_edge, tid); break;
        case 5: stream_phase<5>(rin, rout, s_l4, s_edge, tid); break;
        case 6: stream_phase<6>(rin, rout, s_l4, s_edge, tid); break;
        default: stream_phase<7>(rin, rout, s_l4, s_edge, tid); break;
    }
    __syncthreads();
    if (lb8 != 0 && tid < 128) s_l4[tid * 32] += s_edge[tid];  // b-edges + head
    __syncthreads();

    // ---- Level 3: 512 parents from clamped L4 values ----
    {
        const float4* p = reinterpret_cast<const float4*>(s_l4) + 2 * tid;
        float4 va = p[0], vb = p[1];
        float c0 = __saturatef(va.x), c1 = __saturatef(va.y);
        float c2 = __saturatef(va.z), c3 = __saturatef(va.w);
        float c4 = __saturatef(vb.x), c5 = __saturatef(vb.y);
        float c6 = __saturatef(vb.z), c7 = __saturatef(vb.w);
        const float* swp = g_sw + L4_START + 8 * tid;
        float v = c0 * __ldg(swp + 0) + c1 * __ldg(swp + 1)
                + c2 * __ldg(swp + 2) + c3 * __ldg(swp + 3)
                + c4 * __ldg(swp + 4) + c5 * __ldg(swp + 5)
                + c6 * __ldg(swp + 6) + c7 * __ldg(swp + 7);
        s_l3[tid] = __saturatef(v);
    }
    __syncthreads();

    // ---- Level 2 ----
    if (tid < 64) {
        const float4* p = reinterpret_cast<const float4*>(s_l3) + 2 * tid;
        float4 va = p[0], vb = p[1];
        const float* swp = g_sw + L3_START + 8 * tid;
        float v = va.x * __ldg(swp + 0) + va.y * __ldg(swp + 1)
                + va.z * __ldg(swp + 2) + va.w * __ldg(swp + 3)
                + vb.x * __ldg(swp + 4) + vb.y * __ldg(swp + 5)
                + vb.z * __ldg(swp + 6) + vb.w * __ldg(swp + 7);
        s_l2[tid] = __saturatef(v);
    }
    __syncthreads();

    // ---- Level 1 ----
    if (tid < 8) {
        const float4* p = reinterpret_cast<const float4*>(s_l2) + 2 * tid;
        float4 va = p[0], vb = p[1];
        const float* swp = g_sw + L2_START + 8 * tid;
        float v = va.x * __ldg(swp + 0) + va.y * __ldg(swp + 1)
                + va.z * __ldg(swp + 2) + va.w * __ldg(swp + 3)
                + vb.x * __ldg(swp + 4) + vb.y * __ldg(swp + 5)
                + vb.z * __ldg(swp + 6) + vb.w * __ldg(swp + 7);
        s_l1[tid] = __saturatef(v);
    }
    __syncthreads();

    // ---- Root ----
    if (tid == 0) {
        const float4* p = reinterpret_cast<const float4*>(s_l1);
        float4 va = p[0], vb = p[1];
        const float* swp = g_sw + L1_START;
        float v = va.x * __ldg(swp + 0) + va.y * __ldg(swp + 1)
                + va.z * __ldg(swp + 2) + va.w * __ldg(swp + 3)
                + vb.x * __ldg(swp + 4) + vb.y * __ldg(swp + 5)
                + vb.z * __ldg(swp + 6) + vb.w * __ldg(swp + 7);
        rout[0] = __saturatef(v);
    }

    // ---- Write internal levels (coalesced) ----
    #pragma unroll
    for (int it = 0; it < 8; ++it) {
        int i = it * 512 + tid;
        rout[L4_START + i] = __saturatef(s_l4[i]);
    }
    rout[L3_START + tid] = s_l3[tid];
    if (tid < 64) rout[L2_START + tid] = s_l2[tid];
    if (tid < 8)  rout[L1_START + tid] = s_l1[tid];
}

extern "C" void kernel_launch(void* const* d_in, const int* in_sizes, int n_in,
                              void* d_out, int out_size) {
    const float* probs = (const float*)d_in[0];   // [2048, 37449] fp32
    const float* w     = (const float*)d_in[1];   // [37449] fp32
    float* out         = (float*)d_out;

    const int batch = in_sizes[0] / NN;           // 2048

    setup_kernel<<<(NN + 255) / 256, 256>>>(w);
    tree_kernel<<<batch, 512>>>(probs, out);
}

// round 10
// speedup vs baseline: 1.0918x; 1.0261x over previous
#include <cuda_runtime.h>
#include <cstdint>

#define NN        37449   // total nodes
#define L5_START  4681    // leaf level start
#define L5_COUNT  32768
#define L4_START  585
#define L4_COUNT  4096
#define L3_START  73
#define L2_START  9
#define L1_START  1

// sigmoid(w) for all nodes (internal-level dots + head/tail scalars)
__device__ float g_sw[NN];
// 8 shifted copies of the leaf section: copy s stores leaf l at index
// ((8-s)&7)+l. For LB8=s, vector k's 8 leaves start at copy index
// ((8-s)&7)+s+8k (= 8+8k for s>0, 8k for s=0) -> 32B aligned.
__device__ __align__(32) float g_swl8[8][L5_COUNT + 8];

__global__ void setup_kernel(const float* __restrict__ w) {
    int i = blockIdx.x * blockDim.x + threadIdx.x;
    if (i >= NN) return;
    float sv = 1.0f / (1.0f + __expf(-w[i]));
    g_sw[i] = sv;
    int l = i - L5_START;
    if (l >= 0) {
        #pragma unroll
        for (int s = 0; s < 8; ++s)
            g_swl8[s][((8 - s) & 7) + l] = sv;
    }
}

// ---- 256-bit global memory ops (sm_100+) ----
// Input leaf stream: replay-invariant -> ask L2 to keep it (evict_last).
__device__ __forceinline__ void ldg256_keep(float* v, const float* p) {
    asm volatile("ld.global.nc.L2::evict_last.v8.f32 {%0,%1,%2,%3,%4,%5,%6,%7}, [%8];"
                 : "=f"(v[0]), "=f"(v[1]), "=f"(v[2]), "=f"(v[3]),
                   "=f"(v[4]), "=f"(v[5]), "=f"(v[6]), "=f"(v[7])
                 : "l"(p));
}
__device__ __forceinline__ void ldg256(float* v, const float* p) {
    asm volatile("ld.global.nc.v8.f32 {%0,%1,%2,%3,%4,%5,%6,%7}, [%8];"
                 : "=f"(v[0]), "=f"(v[1]), "=f"(v[2]), "=f"(v[3]),
                   "=f"(v[4]), "=f"(v[5]), "=f"(v[6]), "=f"(v[7])
                 : "l"(p));
}
__device__ __forceinline__ void stg256(float* p, const float* v) {
    asm volatile("st.global.v8.f32 [%0], {%1,%2,%3,%4,%5,%6,%7,%8};"
                 :: "l"(p), "f"(v[0]), "f"(v[1]), "f"(v[2]), "f"(v[3]),
                    "f"(v[4]), "f"(v[5]), "f"(v[6]), "f"(v[7])
                 : "memory");
}

// Vector k covers leaves [LB8+8k, LB8+8k+8): a -> parent k (first 8-LB8
// products), b -> parent k+1 (last LB8 products). Parent k = a[k] + b[k-1].
template<int LB8>
__device__ __forceinline__ void vec_ab(const float* x, const float* sv,
                                       float& a, float& b)
{
    float p[8];
    #pragma unroll
    for (int i = 0; i < 8; ++i) p[i] = x[i] * sv[i];
    a = 0.f; b = 0.f;
    #pragma unroll
    for (int i = 0; i < 8 - LB8; ++i) a += p[i];
    #pragma unroll
    for (int i = 8 - LB8; i < 8; ++i) b += p[i];
}

template<int LB8>
__device__ __forceinline__ void emit(float a, float b, int k,
                                     float* __restrict__ s_l4,
                                     float* __restrict__ s_edge, int lane)
{
    if (LB8 == 0) {
        s_l4[k] = a;                       // vector k IS parent k
    } else {
        float bprev = __shfl_up_sync(0xffffffffu, b, 1);
        float val = a;
        if (lane > 0) val += bprev;        // lane-0 parents patched in fixup
        s_l4[k] = val;
        if (lane == 31) s_edge[(k >> 5) + 1] = b;  // feeds parent k+1
    }
}

template<int LB8>
__device__ __forceinline__ void stream_phase(
    const float* __restrict__ rin, float* __restrict__ rout,
    float* __restrict__ s_l4, float* __restrict__ s_edge, int tid)
{
    const float* __restrict__ xb  = rin  + L5_START + LB8;   // 32B aligned
    float*       __restrict__ ob  = rout + L5_START + LB8;   // 32B aligned
    const float* __restrict__ swb = &g_swl8[LB8][LB8 ? 8 : 0];
    const int lane = tid & 31;

    const int NFULL = (LB8 == 0) ? 8 : 7;   // full 512-vector iterations
    #pragma unroll 2
    for (int it = 0; it < NFULL; ++it) {
        const int k = it * 512 + tid;
        float x[8], sv[8];
        ldg256_keep(x, xb  + 8 * k);
        ldg256(sv,     swb + 8 * k);
        stg256(ob + 8 * k, x);
        float a, b;
        vec_ab<LB8>(x, sv, a, b);
        emit<LB8>(a, b, k, s_l4, s_edge, lane);
    }

    if (LB8 != 0) {
        // Peeled it==7: vector 4095 is clipped (only 8-LB8 leaves exist).
        const int k = 7 * 512 + tid;
        float a, b;
        if (k != 4095) {
            float x[8], sv[8];
            ldg256_keep(x, xb  + 8 * k);
            ldg256(sv,     swb + 8 * k);
            stg256(ob + 8 * k, x);
            vec_ab<LB8>(x, sv, a, b);
        } else {
            const float* rp = xb  + 8 * 4095;
            float*       wp = ob  + 8 * 4095;
            const float* sp = swb + 8 * 4095;
            a = 0.f; b = 0.f;
            #pragma unroll
            for (int j = 0; j < 8 - LB8; ++j) {
                float xv = rp[j];
                wp[j] = xv;
                a += xv * sp[j];
            }
        }
        emit<LB8>(a, b, k, s_l4, s_edge, lane);

        if (tid == 0) {
            // Head leaves 0..LB8-1 belong to parent 0.
            float h = 0.f;
            #pragma unroll
            for (int j = 0; j < LB8; ++j) {
                float xv = rin[L5_START + j];
                rout[L5_START + j] = xv;
                h += xv * g_sw[L5_START + j];
            }
            s_edge[0] = h;
        }
    }
}

__global__ __launch_bounds__(512)
void tree_kernel(const float* __restrict__ in, float* __restrict__ out)
{
    __shared__ __align__(16) float s_l4[L4_COUNT];   // raw (pre-clamp) sums
    __shared__ float s_edge[132];
    __shared__ __align__(16) float s_l3[512];
    __shared__ __align__(16) float s_l2[64];
    __shared__ __align__(16) float s_l1[8];

    const int tid = threadIdx.x;
    const int r   = blockIdx.x;
    const float* __restrict__ rin  = in  + (size_t)r * NN;
    float*       __restrict__ rout = out + (size_t)r * NN;
    const int lb8 = (8 - ((r + 1) & 7)) & 7;   // leaf-base alignment mod 8

    switch (lb8) {
        case 0: stream_phase<0>(rin, rout, s_l4, s_edge, tid); break;
        case 1: stream_phase<1>(rin, rout, s_l4, s_edge, tid); break;
        case 2: stream_phase<2>(rin, rout, s_l4, s_edge, tid); break;
        case 3: stream_phase<3>(rin, rout, s_l4, s_edge, tid); break;
        case 4: stream_phase<4>(rin, rout, s_l4, s_edge, tid); break;
        case 5: stream_phase<5>(rin, rout, s_l4, s_edge, tid); break;
        case 6: stream_phase<6>(rin, rout, s_l4, s_edge, tid); break;
        default: stream_phase<7>(rin, rout, s_l4, s_edge, tid); break;
    }
    __syncthreads();
    if (lb8 != 0 && tid < 128) s_l4[tid * 32] += s_edge[tid];  // b-edges + head
    __syncthreads();

    // ---- Level 3: 512 parents from clamped L4 values ----
    {
        const float4* p = reinterpret_cast<const float4*>(s_l4) + 2 * tid;
        float4 va = p[0], vb = p[1];
        float c0 = __saturatef(va.x), c1 = __saturatef(va.y);
        float c2 = __saturatef(va.z), c3 = __saturatef(va.w);
        float c4 = __saturatef(vb.x), c5 = __saturatef(vb.y);
        float c6 = __saturatef(vb.z), c7 = __saturatef(vb.w);
        const float* swp = g_sw + L4_START + 8 * tid;
        float v = c0 * __ldg(swp + 0) + c1 * __ldg(swp + 1)
                + c2 * __ldg(swp + 2) + c3 * __ldg(swp + 3)
                + c4 * __ldg(swp + 4) + c5 * __ldg(swp + 5)
                + c6 * __ldg(swp + 6) + c7 * __ldg(swp + 7);
        s_l3[tid] = __saturatef(v);
    }
    __syncthreads();

    // ---- Level 2 ----
    if (tid < 64) {
        const float4* p = reinterpret_cast<const float4*>(s_l3) + 2 * tid;
        float4 va = p[0], vb = p[1];
        const float* swp = g_sw + L3_START + 8 * tid;
        float v = va.x * __ldg(swp + 0) + va.y * __ldg(swp + 1)
                + va.z * __ldg(swp + 2) + va.w * __ldg(swp + 3)
                + vb.x * __ldg(swp + 4) + vb.y * __ldg(swp + 5)
                + vb.z * __ldg(swp + 6) + vb.w * __ldg(swp + 7);
        s_l2[tid] = __saturatef(v);
    }
    __syncthreads();

    // ---- Level 1 ----
    if (tid < 8) {
        const float4* p = reinterpret_cast<const float4*>(s_l2) + 2 * tid;
        float4 va = p[0], vb = p[1];
        const float* swp = g_sw + L2_START + 8 * tid;
        float v = va.x * __ldg(swp + 0) + va.y * __ldg(swp + 1)
                + va.z * __ldg(swp + 2) + va.w * __ldg(swp + 3)
                + vb.x * __ldg(swp + 4) + vb.y * __ldg(swp + 5)
                + vb.z * __ldg(swp + 6) + vb.w * __ldg(swp + 7);
        s_l1[tid] = __saturatef(v);
    }
    __syncthreads();

    // ---- Root ----
    if (tid == 0) {
        const float4* p = reinterpret_cast<const float4*>(s_l1);
        float4 va = p[0], vb = p[1];
        const float* swp = g_sw + L1_START;
        float v = va.x * __ldg(swp + 0) + va.y * __ldg(swp + 1)
                + va.z * __ldg(swp + 2) + va.w * __ldg(swp + 3)
                + vb.x * __ldg(swp + 4) + vb.y * __ldg(swp + 5)
                + vb.z * __ldg(swp + 6) + vb.w * __ldg(swp + 7);
        rout[0] = __saturatef(v);
    }

    // ---- Write internal levels (coalesced) ----
    #pragma unroll
    for (int it = 0; it < 8; ++it) {
        int i = it * 512 + tid;
        rout[L4_START + i] = __saturatef(s_l4[i]);
    }
    rout[L3_START + tid] = s_l3[tid];
    if (tid < 64) rout[L2_START + tid] = s_l2[tid];
    if (tid < 8)  rout[L1_START + tid] = s_l1[tid];
}

extern "C" void kernel_launch(void* const* d_in, const int* in_sizes, int n_in,
                              void* d_out, int out_size) {
    const float* probs = (const float*)d_in[0];   // [2048, 37449] fp32
    const float* w     = (const float*)d_in[1];   // [37449] fp32
    float* out         = (float*)d_out;

    const int batch = in_sizes[0] / NN;           // 2048

    setup_kernel<<<(NN + 255) / 256, 256>>>(w);
    tree_kernel<<<batch, 512>>>(probs, out);
}